// round 15
// baseline (speedup 1.0000x reference)
#include <cuda_runtime.h>

// Problem dims
#define NB   8
#define NC   64
#define NT   16
#define NH   56
#define NW   56
#define NHID 128
#define NHP  28
#define NWP  28
#define NK   4

// Kernel-1 tiling
#define IHT  9
#define NPOS (IHT*NW)          // 504
#define CSTR 60                 // 16B-aligned channel stride
#define RSTR (NC*CSTR + 8)      // 3848
#define SX_F (IHT*RSTR)         // 34632
#define WD_F 4096               // [32 cp][32 q][4]: dup pairs per channel-pair
#define BUF_F (32*NPOS)         // 16128
#define SMEM1_F (SX_F + WD_F + BUF_F)   // 54856 floats = 219424 B

// Padded pooled scratch: [b][ch][t][32*32], ring never written (stays 0)
#define PDIM 32
#define PSZ  (PDIM*PDIM)

__device__ float g_pooledP[NB*NHID*NT*PSZ];      // 67 MB, zero-init ring
__device__ float g_e[NB*NT*NHP*NWP];
__device__ int   g_tpos[NB*NK];

// ---------------------------------------------------------------------------
// Kernel 1: conv1x1 (64->128) + bias + ReLU + maxpool 3x3/s2, exact fp32.
// Per-output: sequential c=0..63 ascending FMA chain from 0 (Eigen-exact).
// 512 threads = 16 warps. Warp w: outch group (w&7)*4, position half (w>>3).
// Thread tile: 8 consecutive positions x 4 outch.
// Weights: warp-UNIFORM broadcast, dup pairs packed per channel-pair:
//   swd[(cp*32+q)*4 +{0,1,2,3}] = (w[q][2cp], w[q][2cp], w[q][2cp+1], w[q][2cp+1])
//   -> one broadcast LDS.128 = both channels' f32x2 operands, no MOVs.
// ---------------------------------------------------------------------------
__global__ __launch_bounds__(512, 1) void k_conv_pool(
    const float* __restrict__ x, const float* __restrict__ w1, const float* __restrict__ b1)
{
    extern __shared__ float sm[];
    float* sx  = sm;                 // [9][64][60(+pad)]
    float* swd = sm + SX_F;          // [32 cp][32 q][4]
    float* buf = sm + SX_F + WD_F;   // [32][504]

    int blk = blockIdx.x;
    int ohg = blk % 7;
    int tt  = (blk / 7) % NT;
    int b   = blk / (7*NT);
    int ih0 = ohg*8 - 1;
    int tid = threadIdx.x;

    // vectorized band load: 14 float4 per (r, cc) row
    const float* xbt = x + (b*NC*NT + tt)*(NH*NW);
    for (int i = tid; i < IHT*NC*14; i += 512) {
        int f4  = i % 14;
        int cc  = (i / 14) % NC;
        int r   = i / (14*NC);
        int ih  = ih0 + r;
        float4 v = make_float4(0.f, 0.f, 0.f, 0.f);
        if (ih >= 0 && ih < NH)
            v = __ldg(reinterpret_cast<const float4*>(xbt + cc*(NT*NH*NW) + ih*NW) + f4);
        *reinterpret_cast<float4*>(sx + r*RSTR + cc*CSTR + f4*4) = v;
    }

    int wid  = tid >> 5, lane = tid & 31;
    int qg   = wid & 7;       // outch group: 4 outch (warp-uniform)
    int ph   = wid >> 3;      // position half (0..1)

    int p0 = (ph*32 + lane)*8;          // 8 consecutive positions
    bool val = (p0 < NPOS);             // only ph=1,lane=31 invalid
    int pc = val ? p0 : 0;
    const float* xptr = sx + (pc / NW)*RSTR + (pc % NW);
    const float* wbase = swd + qg*16;   // q = qg*4 .. qg*4+3 -> offset qg*4*4 floats

    for (int it = 0; it < 4; it++) {
        int ch0 = it*32;
        __syncthreads();
        // stage dup-pair weights: entry (q, c) -> swd[((c/2)*32 + q)*4 + (c&1)*2]
        for (int i = tid; i < 32*NC; i += 512) {
            int q = i & 31, cc = i >> 5;
            float v = w1[(ch0 + q)*NC + cc];
            *reinterpret_cast<float2*>(swd + ((cc >> 1)*32 + q)*4 + (cc & 1)*2) = make_float2(v, v);
        }
        __syncthreads();

        unsigned long long acc[4][4];   // [pos-pair][outch]
        #pragma unroll
        for (int pp = 0; pp < 4; pp++)
            #pragma unroll
            for (int qq = 0; qq < 4; qq++) acc[pp][qq] = 0ull;

        #pragma unroll 2
        for (int cp = 0; cp < 32; cp++) {       // channel pair (2cp, 2cp+1)
            ulonglong2 xa = *reinterpret_cast<const ulonglong2*>(xptr + (2*cp)*CSTR);
            ulonglong2 xb = *reinterpret_cast<const ulonglong2*>(xptr + (2*cp)*CSTR + 4);
            ulonglong2 xc = *reinterpret_cast<const ulonglong2*>(xptr + (2*cp+1)*CSTR);
            ulonglong2 xd = *reinterpret_cast<const ulonglong2*>(xptr + (2*cp+1)*CSTR + 4);
            unsigned long long xA[4] = { xa.x, xa.y, xb.x, xb.y };   // ch 2cp
            unsigned long long xB[4] = { xc.x, xc.y, xd.x, xd.y };   // ch 2cp+1
            #pragma unroll
            for (int qq = 0; qq < 4; qq++) {
                ulonglong2 wv = *reinterpret_cast<const ulonglong2*>(wbase + (cp*32 + qq)*4);
                #pragma unroll
                for (int pp = 0; pp < 4; pp++)
                    asm("fma.rn.f32x2 %0, %1, %2, %0;" : "+l"(acc[pp][qq]) : "l"(wv.x), "l"(xA[pp]));
                #pragma unroll
                for (int pp = 0; pp < 4; pp++)
                    asm("fma.rn.f32x2 %0, %1, %2, %0;" : "+l"(acc[pp][qq]) : "l"(wv.y), "l"(xB[pp]));
            }
        }

        // bias + relu -> buf
        #pragma unroll
        for (int qq = 0; qq < 4; qq++) {
            int co = qg*4 + qq;
            float bj = b1[ch0 + co];
            float a[8];
            #pragma unroll
            for (int pp = 0; pp < 4; pp++)
                asm("mov.b64 {%0,%1}, %2;" : "=f"(a[2*pp]), "=f"(a[2*pp+1]) : "l"(acc[pp][qq]));
            #pragma unroll
            for (int k = 0; k < 8; k++) a[k] = fmaxf(__fadd_rn(a[k], bj), 0.f);
            if (val) {
                *reinterpret_cast<float4*>(&buf[co*NPOS + p0])     = make_float4(a[0], a[1], a[2], a[3]);
                *reinterpret_cast<float4*>(&buf[co*NPOS + p0 + 4]) = make_float4(a[4], a[5], a[6], a[7]);
            }
        }
        __syncthreads();

        // maxpool 3x3/s2 pad1 (max is order-exact), write into padded layout
        for (int m = tid; m < 4*28*32; m += 512) {
            int oc  = m % 28;
            int orr = (m / 28) & 3;
            int co  = m / 112;
            float mx = 0.f;
            #pragma unroll
            for (int dy = 0; dy < 3; dy++) {
                int lr = 2*orr + dy;
                int gr = ih0 + lr;
                if (gr < 0 || gr >= NH) continue;
                #pragma unroll
                for (int dx = 0; dx < 3; dx++) {
                    int gc = 2*oc - 1 + dx;
                    if (gc < 0 || gc >= NW) continue;
                    mx = fmaxf(mx, buf[co*NPOS + lr*NW + gc]);
                }
            }
            int ch = ch0 + co;
            g_pooledP[((b*NHID + ch)*NT + tt)*PSZ + (ohg*4 + orr + 1)*PDIM + (oc + 1)] = mx;
        }
    }
}

// ---------------------------------------------------------------------------
// Kernel 2: depthwise 3x3 + bias + ReLU + 1x1 (128->1) + b2.
// Thread-per-position; padded input -> 9 unconditional taps.
// ch = 0..127 sequential chain (no FMA); taps ky,kx ascending (no FMA).
// ---------------------------------------------------------------------------
__global__ __launch_bounds__(784) void k_dw2(
    const float* __restrict__ wd, const float* __restrict__ bd,
    const float* __restrict__ w2, const float* __restrict__ b2)
{
    __shared__ float swdk[NHID*9];
    __shared__ float sbd[NHID], sw2[NHID];

    int bid = blockIdx.x;
    int tt = bid % NT;
    int b  = bid / NT;
    int tid = threadIdx.x;     // position 0..783

    for (int i = tid; i < NHID*9; i += 784) swdk[i] = wd[i];
    if (tid < NHID) { sbd[tid] = bd[tid]; sw2[tid] = w2[tid]; }
    float b2v = b2[0];
    __syncthreads();

    int y = tid / 28, xx = tid % 28;
    const float* base = g_pooledP + (b*NHID*NT + tt)*PSZ + (y+1)*PDIM + (xx+1);
    const int chstride = NT*PSZ;

    float acc = 0.f;
    #pragma unroll 4
    for (int ch = 0; ch < NHID; ch++) {
        const float* p = base + ch*chstride;
        const float* wk = &swdk[ch*9];
        float t0 = __ldg(p - PDIM - 1), t1 = __ldg(p - PDIM), t2 = __ldg(p - PDIM + 1);
        float t3 = __ldg(p - 1),        t4 = __ldg(p),        t5 = __ldg(p + 1);
        float t6 = __ldg(p + PDIM - 1), t7 = __ldg(p + PDIM), t8 = __ldg(p + PDIM + 1);
        float v = 0.f;
        v = __fadd_rn(v, __fmul_rn(wk[0], t0));
        v = __fadd_rn(v, __fmul_rn(wk[1], t1));
        v = __fadd_rn(v, __fmul_rn(wk[2], t2));
        v = __fadd_rn(v, __fmul_rn(wk[3], t3));
        v = __fadd_rn(v, __fmul_rn(wk[4], t4));
        v = __fadd_rn(v, __fmul_rn(wk[5], t5));
        v = __fadd_rn(v, __fmul_rn(wk[6], t6));
        v = __fadd_rn(v, __fmul_rn(wk[7], t7));
        v = __fadd_rn(v, __fmul_rn(wk[8], t8));
        float hv = fmaxf(__fadd_rn(v, sbd[ch]), 0.f);
        acc = __fadd_rn(acc, __fmul_rn(sw2[ch], hv));
    }
    g_e[(b*NT + tt)*784 + tid] = __fadd_rn(acc, b2v);
}

// ---------------------------------------------------------------------------
// Kernel 3: segmentation, XLA:CPU-emitter emulation (bit-identical chains).
// ---------------------------------------------------------------------------
__global__ __launch_bounds__(512) void k_seg(const float* __restrict__ dummy)
{
    extern __shared__ float sm[];
    float* sen = sm;                 // [16][784] ne
    float* cen = sm + 16*784;        // [4][784] centers
    float* snc = sm + 20*784;        // [4][784] normalized centers
    __shared__ float snorm[16], snsim[15], scnorm[4];
    __shared__ float ssims[16][4];
    __shared__ int sgroups[16], sgsize[4];

    int b = blockIdx.x, tid = threadIdx.x;

    for (int i = tid; i < 16*784; i += 512)
        sen[i] = g_e[b*NT*784 + i];
    __syncthreads();

    if (tid < 16) {
        float s = 0.f;
        const float* row = &sen[tid*784];
        for (int d = 0; d < 784; d++) s = __fadd_rn(s, __fmul_rn(row[d], row[d]));
        snorm[tid] = fmaxf(__fsqrt_rn(s), 1e-12f);
    }
    __syncthreads();

    for (int i = tid; i < 16*784; i += 512) sen[i] = __fdiv_rn(sen[i], snorm[i / 784]);
    __syncthreads();

    if (tid < 15) {
        float s = 0.f;
        const float* r0 = &sen[tid*784];
        const float* r1 = &sen[(tid+1)*784];
        for (int d = 0; d < 784; d++) s = __fadd_rn(s, __fmul_rn(r0[d], r1[d]));
        snsim[tid] = s;
    }
    __syncthreads();

    if (tid == 0) {
        int used[15]; int breaks[15];
        for (int i = 0; i < 15; i++) { used[i] = 0; breaks[i] = 0; }
        for (int k = 0; k < 3; k++) {
            float best = 1e30f; int bi = 0;
            for (int i = 0; i < 15; i++)
                if (!used[i] && snsim[i] < best) { best = snsim[i]; bi = i; }
            used[bi] = 1; breaks[bi] = 1;
        }
        int g = 0;
        for (int t = 0; t < 16; t++) { if (t > 0) g += breaks[t-1]; sgroups[t] = g; }
        for (int k = 0; k < 4; k++) sgsize[k] = 0;
        for (int t = 0; t < 16; t++) sgsize[sgroups[t]]++;
    }
    __syncthreads();

    for (int d = tid; d < 784; d += 512) {
        float c4[4] = {0.f, 0.f, 0.f, 0.f};
        for (int t = 0; t < 16; t++)
            c4[sgroups[t]] = __fadd_rn(c4[sgroups[t]], sen[t*784 + d]);
        for (int k = 0; k < 4; k++)
            cen[k*784 + d] = __fdiv_rn(c4[k], (float)sgsize[k]);
    }
    __syncthreads();

    if (tid < 4) {
        float s = 0.f;
        const float* ck = &cen[tid*784];
        for (int d = 0; d < 784; d++) s = __fadd_rn(s, __fmul_rn(ck[d], ck[d]));
        scnorm[tid] = fmaxf(__fsqrt_rn(s), 1e-12f);
    }
    __syncthreads();

    for (int i = tid; i < 4*784; i += 512)
        snc[i] = __fdiv_rn(cen[i], scnorm[i / 784]);
    __syncthreads();

    if (tid < 64) {
        int t = tid / 4, k = tid % 4;
        const float* row = &sen[t*784];
        const float* ck = &snc[k*784];
        float s = 0.f;
        for (int d = 0; d < 784; d++)
            s = __fadd_rn(s, __fmul_rn(row[d], ck[d]));
        ssims[t][k] = fminf(fmaxf(s, -1.f), 1.f);
    }
    __syncthreads();

    if (tid < 4) {
        int k = tid;
        float best = -1e30f; int bt = 0;
        for (int t = 0; t < 16; t++) {
            float v = (sgroups[t] == k) ? ssims[t][k] : 0.f;
            if (v > best) { best = v; bt = t; }
        }
        g_tpos[b*NK + k] = bt;
    }
}

// ---------------------------------------------------------------------------
// Kernel 4: gather selected frames
// ---------------------------------------------------------------------------
__global__ __launch_bounds__(256) void k_gather(const float* __restrict__ x, float* __restrict__ out)
{
    int idx = blockIdx.x*256 + threadIdx.x;
    const int total = NB*NC*NK*784;
    if (idx >= total) return;
    int hw4 = idx % 784;
    int t1  = idx / 784;
    int k   = t1 % 4;  t1 /= 4;
    int c   = t1 % 64;
    int b   = t1 / 64;
    int t   = g_tpos[b*NK + k];
    float4 v = __ldg(reinterpret_cast<const float4*>(x) + ((b*NC + c)*NT + t)*784 + hw4);
    reinterpret_cast<float4*>(out)[idx] = v;
}

// ---------------------------------------------------------------------------
extern "C" void kernel_launch(void* const* d_in, const int* in_sizes, int n_in,
                              void* d_out, int out_size)
{
    const float* x  = (const float*)d_in[0];
    const float* w1 = (const float*)d_in[1];
    const float* b1 = (const float*)d_in[2];
    const float* wd = (const float*)d_in[3];
    const float* bd = (const float*)d_in[4];
    const float* w2 = (const float*)d_in[5];
    const float* b2 = (const float*)d_in[6];
    float* out = (float*)d_out;

    cudaFuncSetAttribute(k_conv_pool, cudaFuncAttributeMaxDynamicSharedMemorySize, SMEM1_F*4);
    cudaFuncSetAttribute(k_seg, cudaFuncAttributeMaxDynamicSharedMemorySize, 24*784*4);

    k_conv_pool<<<NB*NT*7, 512, SMEM1_F*4>>>(x, w1, b1);
    k_dw2<<<NB*NT, 784>>>(wd, bd, w2, b2);
    k_seg<<<NB, 512, 24*784*4>>>(nullptr);
    const int total4 = NB*NC*NK*784;
    k_gather<<<(total4 + 255)/256, 256>>>(x, out);
}

// round 16
// speedup vs baseline: 1.4612x; 1.4612x over previous
#include <cuda_runtime.h>

// Problem dims
#define NB   8
#define NC   64
#define NT   16
#define NH   56
#define NW   56
#define NHID 128
#define NHP  28
#define NWP  28
#define NK   4

// Kernel-1 tiling
#define IHT  9
#define NPOS (IHT*NW)          // 504
#define CSTR 60                 // 16B-aligned channel stride
#define RSTR (NC*CSTR + 8)      // 3848
#define SX_F (IHT*RSTR)         // 34632
#define WD_F (32*NC*2)          // 4096: dup pairs [q][c][2]
#define BUF_F (32*NPOS)         // 16128
#define SMEM1_F (SX_F + WD_F + BUF_F)   // 54856 floats = 219424 B

// Padded pooled scratch: [b][ch][t][32*32], ring never written (stays 0)
#define PDIM 32
#define PSZ  (PDIM*PDIM)

__device__ float g_pooledP[NB*NHID*NT*PSZ];      // 67 MB, zero-init ring
__device__ float g_e[NB*NT*NHP*NWP];
__device__ int   g_tpos[NB*NK];

// ---------------------------------------------------------------------------
// Kernel 1: conv1x1 (64->128) + bias + ReLU + maxpool 3x3/s2, exact fp32.
// Per-output: sequential c=0..63 ascending FMA chain from 0 (Eigen-exact).
// 512 threads = 16 warps: 4 position-groups x 4 outch-subgroups (warp-uniform).
// Thread: 4 consecutive positions (16B lane stride, conflict-free LDS.128)
//         x 8 outch; weights = warp-uniform broadcast dup pairs (no MOVs).
// [R11 configuration — measured 298 us]
// ---------------------------------------------------------------------------
__global__ __launch_bounds__(512, 1) void k_conv_pool(
    const float* __restrict__ x, const float* __restrict__ w1, const float* __restrict__ b1)
{
    extern __shared__ float sm[];
    float* sx  = sm;                 // [9][64][60(+pad)]
    float* swd = sm + SX_F;          // [32 q][64 c][2] dup weight pairs
    float* buf = sm + SX_F + WD_F;   // [32][504]

    int blk = blockIdx.x;
    int ohg = blk % 7;
    int tt  = (blk / 7) % NT;
    int b   = blk / (7*NT);
    int ih0 = ohg*8 - 1;
    int tid = threadIdx.x;

    // vectorized band load: 14 float4 per (r, cc) row
    const float* xbt = x + (b*NC*NT + tt)*(NH*NW);
    for (int i = tid; i < IHT*NC*14; i += 512) {
        int f4  = i % 14;
        int cc  = (i / 14) % NC;
        int r   = i / (14*NC);
        int ih  = ih0 + r;
        float4 v = make_float4(0.f, 0.f, 0.f, 0.f);
        if (ih >= 0 && ih < NH)
            v = __ldg(reinterpret_cast<const float4*>(xbt + cc*(NT*NH*NW) + ih*NW) + f4);
        *reinterpret_cast<float4*>(sx + r*RSTR + cc*CSTR + f4*4) = v;
    }

    int wid  = tid >> 5, lane = tid & 31;
    int grp  = wid >> 2;      // position group (0..3): 128 positions each
    int sub  = wid & 3;       // outch subgroup (0..3): 8 outch (warp-uniform)

    int p0 = grp*128 + lane*4;          // 4 consecutive positions, 16B stride
    bool val = (p0 < NPOS);
    int pc = val ? p0 : 0;
    const float* xptr = sx + (pc / NW)*RSTR + (pc % NW);

    for (int it = 0; it < 4; it++) {
        int ch0 = it*32;
        __syncthreads();
        for (int i = tid; i < 32*NC; i += 512) {
            float v = w1[(ch0 + i/NC)*NC + (i % NC)];
            swd[2*i] = v; swd[2*i+1] = v;
        }
        __syncthreads();

        unsigned long long accA[8], accB[8];
        #pragma unroll
        for (int q = 0; q < 8; q++) { accA[q] = 0ull; accB[q] = 0ull; }

        const float* wbase = swd + (sub*8)*NC*2;
        #pragma unroll 4
        for (int c = 0; c < NC; c += 2) {
            ulonglong2 xa = *reinterpret_cast<const ulonglong2*>(xptr + c*CSTR);
            ulonglong2 xb = *reinterpret_cast<const ulonglong2*>(xptr + (c+1)*CSTR);
            #pragma unroll
            for (int q = 0; q < 8; q++) {
                ulonglong2 wv = *reinterpret_cast<const ulonglong2*>(wbase + (q*NC + c)*2);
                asm("fma.rn.f32x2 %0, %1, %2, %0;" : "+l"(accA[q]) : "l"(wv.x), "l"(xa.x));
                asm("fma.rn.f32x2 %0, %1, %2, %0;" : "+l"(accB[q]) : "l"(wv.x), "l"(xa.y));
                asm("fma.rn.f32x2 %0, %1, %2, %0;" : "+l"(accA[q]) : "l"(wv.y), "l"(xb.x));
                asm("fma.rn.f32x2 %0, %1, %2, %0;" : "+l"(accB[q]) : "l"(wv.y), "l"(xb.y));
            }
        }

        // bias + relu -> buf
        #pragma unroll
        for (int q = 0; q < 8; q++) {
            int co = sub*8 + q;
            float bj = b1[ch0 + co];
            float a0, a1, a2, a3;
            asm("mov.b64 {%0,%1}, %2;" : "=f"(a0), "=f"(a1) : "l"(accA[q]));
            asm("mov.b64 {%0,%1}, %2;" : "=f"(a2), "=f"(a3) : "l"(accB[q]));
            a0 = fmaxf(__fadd_rn(a0, bj), 0.f);
            a1 = fmaxf(__fadd_rn(a1, bj), 0.f);
            a2 = fmaxf(__fadd_rn(a2, bj), 0.f);
            a3 = fmaxf(__fadd_rn(a3, bj), 0.f);
            if (val)
                *reinterpret_cast<float4*>(&buf[co*NPOS + p0]) = make_float4(a0, a1, a2, a3);
        }
        __syncthreads();

        // maxpool 3x3/s2 pad1 (max is order-exact), write into padded layout
        for (int m = tid; m < 4*28*32; m += 512) {
            int oc  = m % 28;
            int orr = (m / 28) & 3;
            int co  = m / 112;
            float mx = 0.f;
            #pragma unroll
            for (int dy = 0; dy < 3; dy++) {
                int lr = 2*orr + dy;
                int gr = ih0 + lr;
                if (gr < 0 || gr >= NH) continue;
                #pragma unroll
                for (int dx = 0; dx < 3; dx++) {
                    int gc = 2*oc - 1 + dx;
                    if (gc < 0 || gc >= NW) continue;
                    mx = fmaxf(mx, buf[co*NPOS + lr*NW + gc]);
                }
            }
            int ch = ch0 + co;
            g_pooledP[((b*NHID + ch)*NT + tt)*PSZ + (ohg*4 + orr + 1)*PDIM + (oc + 1)] = mx;
        }
    }
}

// ---------------------------------------------------------------------------
// Kernel 2: depthwise 3x3 + bias + ReLU + 1x1 (128->1) + b2.
// Thread-per-position; padded input -> 9 unconditional taps.
// ch = 0..127 sequential chain (no FMA); taps ky,kx ascending (no FMA).
// [measured 52.8 us]
// ---------------------------------------------------------------------------
__global__ __launch_bounds__(784) void k_dw2(
    const float* __restrict__ wd, const float* __restrict__ bd,
    const float* __restrict__ w2, const float* __restrict__ b2)
{
    __shared__ float swdk[NHID*9];
    __shared__ float sbd[NHID], sw2[NHID];

    int bid = blockIdx.x;
    int tt = bid % NT;
    int b  = bid / NT;
    int tid = threadIdx.x;     // position 0..783

    for (int i = tid; i < NHID*9; i += 784) swdk[i] = wd[i];
    if (tid < NHID) { sbd[tid] = bd[tid]; sw2[tid] = w2[tid]; }
    float b2v = b2[0];
    __syncthreads();

    int y = tid / 28, xx = tid % 28;
    const float* base = g_pooledP + (b*NHID*NT + tt)*PSZ + (y+1)*PDIM + (xx+1);
    const int chstride = NT*PSZ;

    float acc = 0.f;
    #pragma unroll 4
    for (int ch = 0; ch < NHID; ch++) {
        const float* p = base + ch*chstride;
        const float* wk = &swdk[ch*9];
        float t0 = __ldg(p - PDIM - 1), t1 = __ldg(p - PDIM), t2 = __ldg(p - PDIM + 1);
        float t3 = __ldg(p - 1),        t4 = __ldg(p),        t5 = __ldg(p + 1);
        float t6 = __ldg(p + PDIM - 1), t7 = __ldg(p + PDIM), t8 = __ldg(p + PDIM + 1);
        float v = 0.f;
        v = __fadd_rn(v, __fmul_rn(wk[0], t0));
        v = __fadd_rn(v, __fmul_rn(wk[1], t1));
        v = __fadd_rn(v, __fmul_rn(wk[2], t2));
        v = __fadd_rn(v, __fmul_rn(wk[3], t3));
        v = __fadd_rn(v, __fmul_rn(wk[4], t4));
        v = __fadd_rn(v, __fmul_rn(wk[5], t5));
        v = __fadd_rn(v, __fmul_rn(wk[6], t6));
        v = __fadd_rn(v, __fmul_rn(wk[7], t7));
        v = __fadd_rn(v, __fmul_rn(wk[8], t8));
        float hv = fmaxf(__fadd_rn(v, sbd[ch]), 0.f);
        acc = __fadd_rn(acc, __fmul_rn(sw2[ch], hv));
    }
    g_e[(b*NT + tt)*784 + tid] = __fadd_rn(acc, b2v);
}

// ---------------------------------------------------------------------------
// Kernel 3: segmentation, XLA:CPU-emitter emulation (bit-identical chains).
// ---------------------------------------------------------------------------
__global__ __launch_bounds__(512) void k_seg(const float* __restrict__ dummy)
{
    extern __shared__ float sm[];
    float* sen = sm;                 // [16][784] ne
    float* cen = sm + 16*784;        // [4][784] centers
    float* snc = sm + 20*784;        // [4][784] normalized centers
    __shared__ float snorm[16], snsim[15], scnorm[4];
    __shared__ float ssims[16][4];
    __shared__ int sgroups[16], sgsize[4];

    int b = blockIdx.x, tid = threadIdx.x;

    for (int i = tid; i < 16*784; i += 512)
        sen[i] = g_e[b*NT*784 + i];
    __syncthreads();

    if (tid < 16) {
        float s = 0.f;
        const float* row = &sen[tid*784];
        for (int d = 0; d < 784; d++) s = __fadd_rn(s, __fmul_rn(row[d], row[d]));
        snorm[tid] = fmaxf(__fsqrt_rn(s), 1e-12f);
    }
    __syncthreads();

    for (int i = tid; i < 16*784; i += 512) sen[i] = __fdiv_rn(sen[i], snorm[i / 784]);
    __syncthreads();

    if (tid < 15) {
        float s = 0.f;
        const float* r0 = &sen[tid*784];
        const float* r1 = &sen[(tid+1)*784];
        for (int d = 0; d < 784; d++) s = __fadd_rn(s, __fmul_rn(r0[d], r1[d]));
        snsim[tid] = s;
    }
    __syncthreads();

    if (tid == 0) {
        int used[15]; int breaks[15];
        for (int i = 0; i < 15; i++) { used[i] = 0; breaks[i] = 0; }
        for (int k = 0; k < 3; k++) {
            float best = 1e30f; int bi = 0;
            for (int i = 0; i < 15; i++)
                if (!used[i] && snsim[i] < best) { best = snsim[i]; bi = i; }
            used[bi] = 1; breaks[bi] = 1;
        }
        int g = 0;
        for (int t = 0; t < 16; t++) { if (t > 0) g += breaks[t-1]; sgroups[t] = g; }
        for (int k = 0; k < 4; k++) sgsize[k] = 0;
        for (int t = 0; t < 16; t++) sgsize[sgroups[t]]++;
    }
    __syncthreads();

    for (int d = tid; d < 784; d += 512) {
        float c4[4] = {0.f, 0.f, 0.f, 0.f};
        for (int t = 0; t < 16; t++)
            c4[sgroups[t]] = __fadd_rn(c4[sgroups[t]], sen[t*784 + d]);
        for (int k = 0; k < 4; k++)
            cen[k*784 + d] = __fdiv_rn(c4[k], (float)sgsize[k]);
    }
    __syncthreads();

    if (tid < 4) {
        float s = 0.f;
        const float* ck = &cen[tid*784];
        for (int d = 0; d < 784; d++) s = __fadd_rn(s, __fmul_rn(ck[d], ck[d]));
        scnorm[tid] = fmaxf(__fsqrt_rn(s), 1e-12f);
    }
    __syncthreads();

    for (int i = tid; i < 4*784; i += 512)
        snc[i] = __fdiv_rn(cen[i], scnorm[i / 784]);
    __syncthreads();

    if (tid < 64) {
        int t = tid / 4, k = tid % 4;
        const float* row = &sen[t*784];
        const float* ck = &snc[k*784];
        float s = 0.f;
        for (int d = 0; d < 784; d++)
            s = __fadd_rn(s, __fmul_rn(row[d], ck[d]));
        ssims[t][k] = fminf(fmaxf(s, -1.f), 1.f);
    }
    __syncthreads();

    if (tid < 4) {
        int k = tid;
        float best = -1e30f; int bt = 0;
        for (int t = 0; t < 16; t++) {
            float v = (sgroups[t] == k) ? ssims[t][k] : 0.f;
            if (v > best) { best = v; bt = t; }
        }
        g_tpos[b*NK + k] = bt;
    }
}

// ---------------------------------------------------------------------------
// Kernel 4: gather selected frames
// ---------------------------------------------------------------------------
__global__ __launch_bounds__(256) void k_gather(const float* __restrict__ x, float* __restrict__ out)
{
    int idx = blockIdx.x*256 + threadIdx.x;
    const int total = NB*NC*NK*784;
    if (idx >= total) return;
    int hw4 = idx % 784;
    int t1  = idx / 784;
    int k   = t1 % 4;  t1 /= 4;
    int c   = t1 % 64;
    int b   = t1 / 64;
    int t   = g_tpos[b*NK + k];
    float4 v = __ldg(reinterpret_cast<const float4*>(x) + ((b*NC + c)*NT + t)*784 + hw4);
    reinterpret_cast<float4*>(out)[idx] = v;
}

// ---------------------------------------------------------------------------
extern "C" void kernel_launch(void* const* d_in, const int* in_sizes, int n_in,
                              void* d_out, int out_size)
{
    const float* x  = (const float*)d_in[0];
    const float* w1 = (const float*)d_in[1];
    const float* b1 = (const float*)d_in[2];
    const float* wd = (const float*)d_in[3];
    const float* bd = (const float*)d_in[4];
    const float* w2 = (const float*)d_in[5];
    const float* b2 = (const float*)d_in[6];
    float* out = (float*)d_out;

    cudaFuncSetAttribute(k_conv_pool, cudaFuncAttributeMaxDynamicSharedMemorySize, SMEM1_F*4);
    cudaFuncSetAttribute(k_seg, cudaFuncAttributeMaxDynamicSharedMemorySize, 24*784*4);

    k_conv_pool<<<NB*NT*7, 512, SMEM1_F*4>>>(x, w1, b1);
    k_dw2<<<NB*NT, 784>>>(wd, bd, w2, b2);
    k_seg<<<NB, 512, 24*784*4>>>(nullptr);
    const int total4 = NB*NC*NK*784;
    k_gather<<<(total4 + 255)/256, 256>>>(x, out);
}

// round 17
// speedup vs baseline: 1.4869x; 1.0176x over previous
#include <cuda_runtime.h>

// Problem dims
#define NB   8
#define NC   64
#define NT   16
#define NH   56
#define NW   56
#define NHID 128
#define NHP  28
#define NWP  28
#define NK   4

// Kernel-1 tiling
#define IHT  9
#define NPOS (IHT*NW)          // 504
#define CSTR 60                 // 16B-aligned channel stride
#define RSTR (NC*CSTR + 8)      // 3848
#define SX_F (IHT*RSTR)         // 34632
#define WD_F (32*NC*2)          // 4096: dup pairs [q][c][2]
#define BUF_F (32*NPOS)         // 16128
#define SMEM1_F (SX_F + WD_F + BUF_F)   // 54856 floats = 219424 B

// Padded pooled scratch: [b][ch][t][32*32], ring never written (stays 0)
#define PDIM 32
#define PSZ  (PDIM*PDIM)

__device__ float g_pooledP[NB*NHID*NT*PSZ];      // 67 MB, zero-init ring
__device__ float g_epart[2*NB*NT*NHP*NWP];       // two channel-halves of e-dot
__device__ int   g_tpos[NB*NK];

// ---------------------------------------------------------------------------
// Kernel 1: conv1x1 (64->128) + bias + ReLU + maxpool 3x3/s2, exact fp32.
// Per-output: sequential c=0..63 ascending FMA chain from 0 (Eigen-exact).
// 512 threads = 16 warps: 4 position-groups x 4 outch-subgroups (warp-uniform).
// Thread: 4 consecutive positions (16B lane stride, conflict-free LDS.128)
//         x 8 outch; weights = warp-uniform broadcast dup pairs (no MOVs).
// [measured ~280 us — crossbar+FMA both saturated; architecture floor]
// ---------------------------------------------------------------------------
__global__ __launch_bounds__(512, 1) void k_conv_pool(
    const float* __restrict__ x, const float* __restrict__ w1, const float* __restrict__ b1)
{
    extern __shared__ float sm[];
    float* sx  = sm;                 // [9][64][60(+pad)]
    float* swd = sm + SX_F;          // [32 q][64 c][2] dup weight pairs
    float* buf = sm + SX_F + WD_F;   // [32][504]

    int blk = blockIdx.x;
    int ohg = blk % 7;
    int tt  = (blk / 7) % NT;
    int b   = blk / (7*NT);
    int ih0 = ohg*8 - 1;
    int tid = threadIdx.x;

    // vectorized band load: 14 float4 per (r, cc) row
    const float* xbt = x + (b*NC*NT + tt)*(NH*NW);
    for (int i = tid; i < IHT*NC*14; i += 512) {
        int f4  = i % 14;
        int cc  = (i / 14) % NC;
        int r   = i / (14*NC);
        int ih  = ih0 + r;
        float4 v = make_float4(0.f, 0.f, 0.f, 0.f);
        if (ih >= 0 && ih < NH)
            v = __ldg(reinterpret_cast<const float4*>(xbt + cc*(NT*NH*NW) + ih*NW) + f4);
        *reinterpret_cast<float4*>(sx + r*RSTR + cc*CSTR + f4*4) = v;
    }

    int wid  = tid >> 5, lane = tid & 31;
    int grp  = wid >> 2;      // position group (0..3): 128 positions each
    int sub  = wid & 3;       // outch subgroup (0..3): 8 outch (warp-uniform)

    int p0 = grp*128 + lane*4;          // 4 consecutive positions, 16B stride
    bool val = (p0 < NPOS);
    int pc = val ? p0 : 0;
    const float* xptr = sx + (pc / NW)*RSTR + (pc % NW);

    for (int it = 0; it < 4; it++) {
        int ch0 = it*32;
        __syncthreads();
        for (int i = tid; i < 32*NC; i += 512) {
            float v = w1[(ch0 + i/NC)*NC + (i % NC)];
            swd[2*i] = v; swd[2*i+1] = v;
        }
        __syncthreads();

        unsigned long long accA[8], accB[8];
        #pragma unroll
        for (int q = 0; q < 8; q++) { accA[q] = 0ull; accB[q] = 0ull; }

        const float* wbase = swd + (sub*8)*NC*2;
        #pragma unroll 4
        for (int c = 0; c < NC; c += 2) {
            ulonglong2 xa = *reinterpret_cast<const ulonglong2*>(xptr + c*CSTR);
            ulonglong2 xb = *reinterpret_cast<const ulonglong2*>(xptr + (c+1)*CSTR);
            #pragma unroll
            for (int q = 0; q < 8; q++) {
                ulonglong2 wv = *reinterpret_cast<const ulonglong2*>(wbase + (q*NC + c)*2);
                asm("fma.rn.f32x2 %0, %1, %2, %0;" : "+l"(accA[q]) : "l"(wv.x), "l"(xa.x));
                asm("fma.rn.f32x2 %0, %1, %2, %0;" : "+l"(accB[q]) : "l"(wv.x), "l"(xa.y));
                asm("fma.rn.f32x2 %0, %1, %2, %0;" : "+l"(accA[q]) : "l"(wv.y), "l"(xb.x));
                asm("fma.rn.f32x2 %0, %1, %2, %0;" : "+l"(accB[q]) : "l"(wv.y), "l"(xb.y));
            }
        }

        // bias + relu -> buf
        #pragma unroll
        for (int q = 0; q < 8; q++) {
            int co = sub*8 + q;
            float bj = b1[ch0 + co];
            float a0, a1, a2, a3;
            asm("mov.b64 {%0,%1}, %2;" : "=f"(a0), "=f"(a1) : "l"(accA[q]));
            asm("mov.b64 {%0,%1}, %2;" : "=f"(a2), "=f"(a3) : "l"(accB[q]));
            a0 = fmaxf(__fadd_rn(a0, bj), 0.f);
            a1 = fmaxf(__fadd_rn(a1, bj), 0.f);
            a2 = fmaxf(__fadd_rn(a2, bj), 0.f);
            a3 = fmaxf(__fadd_rn(a3, bj), 0.f);
            if (val)
                *reinterpret_cast<float4*>(&buf[co*NPOS + p0]) = make_float4(a0, a1, a2, a3);
        }
        __syncthreads();

        // maxpool 3x3/s2 pad1 (max is order-exact), write into padded layout
        for (int m = tid; m < 4*28*32; m += 512) {
            int oc  = m % 28;
            int orr = (m / 28) & 3;
            int co  = m / 112;
            float mx = 0.f;
            #pragma unroll
            for (int dy = 0; dy < 3; dy++) {
                int lr = 2*orr + dy;
                int gr = ih0 + lr;
                if (gr < 0 || gr >= NH) continue;
                #pragma unroll
                for (int dx = 0; dx < 3; dx++) {
                    int gc = 2*oc - 1 + dx;
                    if (gc < 0 || gc >= NW) continue;
                    mx = fmaxf(mx, buf[co*NPOS + lr*NW + gc]);
                }
            }
            int ch = ch0 + co;
            g_pooledP[((b*NHID + ch)*NT + tt)*PSZ + (ohg*4 + orr + 1)*PDIM + (oc + 1)] = mx;
        }
    }
}

// ---------------------------------------------------------------------------
// Kernel 2: depthwise 3x3 + bias + ReLU + 1x1 (128->1), channel-half split.
// 256 blocks (b, t, half): half h covers ch h*64..h*64+63, sequential chain
// (no FMA) into g_epart[h] — the proven R7 decomposition (passed rel_err 0).
// Two 784-thread blocks co-reside per SM -> 49 warps, all 148 SMs used.
// ---------------------------------------------------------------------------
__global__ __launch_bounds__(784) void k_dw2(
    const float* __restrict__ wd, const float* __restrict__ bd,
    const float* __restrict__ w2)
{
    __shared__ float swdk[64*9];
    __shared__ float sbd[64], sw2[64];

    int bid = blockIdx.x;
    int h  = bid & 1;
    int tt = (bid >> 1) % NT;
    int b  = bid / (2*NT);
    int tid = threadIdx.x;     // position 0..783
    int ch0 = h*64;

    for (int i = tid; i < 64*9; i += 784) swdk[i] = wd[ch0*9 + i];
    if (tid < 64) { sbd[tid] = bd[ch0 + tid]; sw2[tid] = w2[ch0 + tid]; }
    __syncthreads();

    int y = tid / 28, xx = tid % 28;
    const float* base = g_pooledP + ((b*NHID + ch0)*NT + tt)*PSZ + (y+1)*PDIM + (xx+1);
    const int chstride = NT*PSZ;

    float acc = 0.f;
    #pragma unroll 4
    for (int ch = 0; ch < 64; ch++) {
        const float* p = base + ch*chstride;
        const float* wk = &swdk[ch*9];
        float t0 = __ldg(p - PDIM - 1), t1 = __ldg(p - PDIM), t2 = __ldg(p - PDIM + 1);
        float t3 = __ldg(p - 1),        t4 = __ldg(p),        t5 = __ldg(p + 1);
        float t6 = __ldg(p + PDIM - 1), t7 = __ldg(p + PDIM), t8 = __ldg(p + PDIM + 1);
        float v = 0.f;
        v = __fadd_rn(v, __fmul_rn(wk[0], t0));
        v = __fadd_rn(v, __fmul_rn(wk[1], t1));
        v = __fadd_rn(v, __fmul_rn(wk[2], t2));
        v = __fadd_rn(v, __fmul_rn(wk[3], t3));
        v = __fadd_rn(v, __fmul_rn(wk[4], t4));
        v = __fadd_rn(v, __fmul_rn(wk[5], t5));
        v = __fadd_rn(v, __fmul_rn(wk[6], t6));
        v = __fadd_rn(v, __fmul_rn(wk[7], t7));
        v = __fadd_rn(v, __fmul_rn(wk[8], t8));
        float hv = fmaxf(__fadd_rn(v, sbd[ch]), 0.f);
        acc = __fadd_rn(acc, __fmul_rn(sw2[ch], hv));
    }
    g_epart[((h*NB + b)*NT + tt)*784 + tid] = acc;
}

// ---------------------------------------------------------------------------
// Kernel 3: segmentation, XLA:CPU-emitter emulation (bit-identical chains).
// e = (part0 + part1) + b2 — the R7 construction (passed rel_err 0).
// ---------------------------------------------------------------------------
__global__ __launch_bounds__(512) void k_seg(const float* __restrict__ b2)
{
    extern __shared__ float sm[];
    float* sen = sm;                 // [16][784] ne
    float* cen = sm + 16*784;        // [4][784] centers
    float* snc = sm + 20*784;        // [4][784] normalized centers
    __shared__ float snorm[16], snsim[15], scnorm[4];
    __shared__ float ssims[16][4];
    __shared__ int sgroups[16], sgsize[4];

    int b = blockIdx.x, tid = threadIdx.x;
    float b2v = b2[0];

    for (int i = tid; i < 16*784; i += 512) {
        int tt = i / 784, p = i % 784;
        sen[i] = __fadd_rn(__fadd_rn(g_epart[(b*NT + tt)*784 + p],
                                     g_epart[((NB + b)*NT + tt)*784 + p]), b2v);
    }
    __syncthreads();

    if (tid < 16) {
        float s = 0.f;
        const float* row = &sen[tid*784];
        for (int d = 0; d < 784; d++) s = __fadd_rn(s, __fmul_rn(row[d], row[d]));
        snorm[tid] = fmaxf(__fsqrt_rn(s), 1e-12f);
    }
    __syncthreads();

    for (int i = tid; i < 16*784; i += 512) sen[i] = __fdiv_rn(sen[i], snorm[i / 784]);
    __syncthreads();

    if (tid < 15) {
        float s = 0.f;
        const float* r0 = &sen[tid*784];
        const float* r1 = &sen[(tid+1)*784];
        for (int d = 0; d < 784; d++) s = __fadd_rn(s, __fmul_rn(r0[d], r1[d]));
        snsim[tid] = s;
    }
    __syncthreads();

    if (tid == 0) {
        int used[15]; int breaks[15];
        for (int i = 0; i < 15; i++) { used[i] = 0; breaks[i] = 0; }
        for (int k = 0; k < 3; k++) {
            float best = 1e30f; int bi = 0;
            for (int i = 0; i < 15; i++)
                if (!used[i] && snsim[i] < best) { best = snsim[i]; bi = i; }
            used[bi] = 1; breaks[bi] = 1;
        }
        int g = 0;
        for (int t = 0; t < 16; t++) { if (t > 0) g += breaks[t-1]; sgroups[t] = g; }
        for (int k = 0; k < 4; k++) sgsize[k] = 0;
        for (int t = 0; t < 16; t++) sgsize[sgroups[t]]++;
    }
    __syncthreads();

    for (int d = tid; d < 784; d += 512) {
        float c4[4] = {0.f, 0.f, 0.f, 0.f};
        for (int t = 0; t < 16; t++)
            c4[sgroups[t]] = __fadd_rn(c4[sgroups[t]], sen[t*784 + d]);
        for (int k = 0; k < 4; k++)
            cen[k*784 + d] = __fdiv_rn(c4[k], (float)sgsize[k]);
    }
    __syncthreads();

    if (tid < 4) {
        float s = 0.f;
        const float* ck = &cen[tid*784];
        for (int d = 0; d < 784; d++) s = __fadd_rn(s, __fmul_rn(ck[d], ck[d]));
        scnorm[tid] = fmaxf(__fsqrt_rn(s), 1e-12f);
    }
    __syncthreads();

    for (int i = tid; i < 4*784; i += 512)
        snc[i] = __fdiv_rn(cen[i], scnorm[i / 784]);
    __syncthreads();

    if (tid < 64) {
        int t = tid / 4, k = tid % 4;
        const float* row = &sen[t*784];
        const float* ck = &snc[k*784];
        float s = 0.f;
        for (int d = 0; d < 784; d++)
            s = __fadd_rn(s, __fmul_rn(row[d], ck[d]));
        ssims[t][k] = fminf(fmaxf(s, -1.f), 1.f);
    }
    __syncthreads();

    if (tid < 4) {
        int k = tid;
        float best = -1e30f; int bt = 0;
        for (int t = 0; t < 16; t++) {
            float v = (sgroups[t] == k) ? ssims[t][k] : 0.f;
            if (v > best) { best = v; bt = t; }
        }
        g_tpos[b*NK + k] = bt;
    }
}

// ---------------------------------------------------------------------------
// Kernel 4: gather selected frames
// ---------------------------------------------------------------------------
__global__ __launch_bounds__(256) void k_gather(const float* __restrict__ x, float* __restrict__ out)
{
    int idx = blockIdx.x*256 + threadIdx.x;
    const int total = NB*NC*NK*784;
    if (idx >= total) return;
    int hw4 = idx % 784;
    int t1  = idx / 784;
    int k   = t1 % 4;  t1 /= 4;
    int c   = t1 % 64;
    int b   = t1 / 64;
    int t   = g_tpos[b*NK + k];
    float4 v = __ldg(reinterpret_cast<const float4*>(x) + ((b*NC + c)*NT + t)*784 + hw4);
    reinterpret_cast<float4*>(out)[idx] = v;
}

// ---------------------------------------------------------------------------
extern "C" void kernel_launch(void* const* d_in, const int* in_sizes, int n_in,
                              void* d_out, int out_size)
{
    const float* x  = (const float*)d_in[0];
    const float* w1 = (const float*)d_in[1];
    const float* b1 = (const float*)d_in[2];
    const float* wd = (const float*)d_in[3];
    const float* bd = (const float*)d_in[4];
    const float* w2 = (const float*)d_in[5];
    const float* b2 = (const float*)d_in[6];
    float* out = (float*)d_out;

    cudaFuncSetAttribute(k_conv_pool, cudaFuncAttributeMaxDynamicSharedMemorySize, SMEM1_F*4);
    cudaFuncSetAttribute(k_seg, cudaFuncAttributeMaxDynamicSharedMemorySize, 24*784*4);

    k_conv_pool<<<NB*NT*7, 512, SMEM1_F*4>>>(x, w1, b1);
    k_dw2<<<NB*NT*2, 784>>>(wd, bd, w2);
    k_seg<<<NB, 512, 24*784*4>>>(b2);
    const int total4 = NB*NC*NK*784;
    k_gather<<<(total4 + 255)/256, 256>>>(x, out);
}